// round 12
// baseline (speedup 1.0000x reference)
#include <cuda_runtime.h>
#include <cuda_fp16.h>
#include <math.h>
#include <stdint.h>

#define MAXN 50000
#define MAXE 400000

// ---------------- static scratch (all intermediates fp16) ----------------
__device__ __half g_xh[MAXN * 64];
__device__ __half g_agg0[MAXN * 64];
__device__ __half g_T1[MAXN * 256];
__device__ __half g_agg1[MAXN * 256];
__device__ __half g_Vf[MAXN * 320];      // V (0:256) | xh (256:320)
__device__ __half g_H[MAXN * 128];
__device__ float g_dis[MAXN];
__device__ int g_cnt[MAXN], g_rowptr[MAXN + 1], g_cursor[MAXN], g_csrsrc[MAXE];
__device__ float g_csrnorm[MAXE];
__device__ int g_bsum[64];
__device__ int g_mv[256];
__device__ __half g_WcT[256 * 64];
__device__ __half g_W2T[256 * 128];
__device__ __half g_W4T[256 * 128];
__device__ __half g_W7T[128 * 320];
__device__ float g_bc[256];

// ---------------- helpers ----------------
__device__ __forceinline__ uint32_t smem_u32(const void* p) {
    uint32_t a;
    asm("{ .reg .u64 t; cvta.to.shared.u64 t, %1; cvt.u32.u64 %0, t; }" : "=r"(a) : "l"(p));
    return a;
}
__device__ __forceinline__ void cpasync16(uint32_t dst, const void* src, bool pred) {
    int sz = pred ? 16 : 0;
    asm volatile("cp.async.cg.shared.global [%0], [%1], 16, %2;\n" :: "r"(dst), "l"(src), "r"(sz));
}
__device__ __forceinline__ void ldmx4(uint32_t& r0, uint32_t& r1, uint32_t& r2, uint32_t& r3,
                                      uint32_t addr) {
    asm volatile("ldmatrix.sync.aligned.m8n8.x4.shared.b16 {%0,%1,%2,%3}, [%4];"
                 : "=r"(r0), "=r"(r1), "=r"(r2), "=r"(r3) : "r"(addr));
}
__device__ __forceinline__ void mma16816(float* c, const uint32_t* a, const uint32_t* b) {
    asm volatile(
        "mma.sync.aligned.m16n8k16.row.col.f32.f16.f16.f32 "
        "{%0,%1,%2,%3}, {%4,%5,%6,%7}, {%8,%9}, {%0,%1,%2,%3};"
        : "+f"(c[0]), "+f"(c[1]), "+f"(c[2]), "+f"(c[3])
        : "r"(a[0]), "r"(a[1]), "r"(a[2]), "r"(a[3]), "r"(b[0]), "r"(b[1]));
}

// ---------------- CSR build ----------------
__global__ void count_kernel(const int* __restrict__ dst, int e, int* __restrict__ cnt) {
    int i = blockIdx.x * blockDim.x + threadIdx.x;
    if (i < e) atomicAdd(&cnt[dst[i]], 1);
}

__global__ void scan_fused_kernel(const int* __restrict__ cnt, int n, int* __restrict__ bsum,
                                  int* __restrict__ rowptr, int* __restrict__ cursor,
                                  float* __restrict__ dis) {
    int tid = threadIdx.x;
    int lane = tid & 31, warp = tid >> 5;
    int base = (blockIdx.x * 256 + tid) * 16;
    int vals[16];
    int s = 0;
#pragma unroll
    for (int i = 0; i < 16; i++) {
        int idx = base + i;
        vals[i] = (idx < n) ? cnt[idx] : 0;
        s += vals[i];
    }
    int incl = s;
#pragma unroll
    for (int o = 1; o < 32; o <<= 1) {
        int t = __shfl_up_sync(0xffffffffu, incl, o);
        if (lane >= o) incl += t;
    }
    __shared__ int wsum[8];
    if (lane == 31) wsum[warp] = incl;
    __syncthreads();
    int woff = 0, total = 0;
#pragma unroll
    for (int w = 0; w < 8; w++) {
        if (w < warp) woff += wsum[w];
        total += wsum[w];
    }
    __shared__ int sPre;
    if (tid == 0) {
        atomicExch(&bsum[blockIdx.x], total + 1);
        int pre = 0;
        for (int w = 0; w < (int)blockIdx.x; w++) {
            int v;
            do { v = atomicAdd(&bsum[w], 0); } while (v == 0);
            pre += v - 1;
        }
        sPre = pre;
    }
    __syncthreads();
    int excl = sPre + woff + (incl - s);
#pragma unroll
    for (int i = 0; i < 16; i++) {
        int idx = base + i;
        if (idx < n) {
            rowptr[idx] = excl;
            cursor[idx] = excl;
            dis[idx] = rsqrtf((float)(vals[i] + 1));
            excl += vals[i];
        }
    }
    if (blockIdx.x == gridDim.x - 1 && tid == 0) rowptr[n] = sPre + total;
}

__global__ void fill_kernel(const int* __restrict__ src, const int* __restrict__ dst, int e,
                            int* __restrict__ cursor, int* __restrict__ csrsrc,
                            float* __restrict__ csrnorm, const float* __restrict__ dis) {
    int i = blockIdx.x * blockDim.x + threadIdx.x;
    if (i >= e) return;
    int d = dst[i], s = src[i];
    int p = atomicAdd(&cursor[d], 1);
    csrsrc[p] = s;
    csrnorm[p] = dis[s] * dis[d];
}

// ---------------- merged weight + x conversion ----------------
__global__ void conv_kernel(const float* __restrict__ W1, const float* __restrict__ W3,
                            const float* __restrict__ W2, const float* __restrict__ W4,
                            const float* __restrict__ W7, const float* __restrict__ b1,
                            const float* __restrict__ b3, const float* __restrict__ x,
                            __half* WcT, __half* W2T, __half* W4T, __half* W7T,
                            float* bc, __half* xh, __half* Vf, int xtotal) {
    int i = blockIdx.x * blockDim.x + threadIdx.x;
    if (i < 256) bc[i] = (i < 128) ? b1[i] : b3[i - 128];
    if (i < 122880) {  // weights
        float v;
        __half* o;
        int off;
        if (i < 16384) {
            int c = i >> 6, k = i & 63;
            v = (c < 128) ? W1[k * 128 + c] : W3[k * 128 + (c - 128)];
            o = WcT; off = i;
        } else if (i < 49152) {
            int j = i - 16384; int c = j >> 7, k = j & 127;
            v = W2[k * 256 + c]; o = W2T; off = j;
        } else if (i < 81920) {
            int j = i - 49152; int c = j >> 7, k = j & 127;
            v = W4[k * 256 + c]; o = W4T; off = j;
        } else {
            int j = i - 81920; int c = j / 320, k = j % 320;
            v = (k < 256) ? W7[(size_t)(256 + k) * 128 + c]
                          : W7[(size_t)(512 + (k - 256)) * 128 + c];
            o = W7T; off = j;
        }
        o[off] = __float2half_rn(v);
    } else {
        int j = i - 122880;
        if (j >= xtotal) return;
        int row = j >> 6, c = j & 63;
        __half h = __float2half_rn(x[j]);
        xh[j] = h;
        Vf[(size_t)row * 320 + 256 + c] = h;
    }
}

// ---------------- HMMA mainloop (pure fp16, 128x128x32) ----------------
__device__ __forceinline__ void gemm_mainloop(
    const __half* __restrict__ A, int lda,
    const __half* __restrict__ B,
    int K, int n, int rowBase, int colBase,
    __half (*As)[128 * 40], __half (*Bs)[128 * 40],
    float acc[4][4][4]) {
    int tid = threadIdx.x;
    int lane = tid & 31, warp = tid >> 5;
    int warpM = warp & 1, warpN = warp >> 1;
    int total = K >> 5;

    auto loadChunk = [&](int kc, int buf) {
        int k0 = kc << 5;
        uint32_t aB = smem_u32(&As[buf][0]);
        uint32_t bB = smem_u32(&Bs[buf][0]);
#pragma unroll
        for (int i = 0; i < 2; i++) {
            int idx = tid + (i << 8);
            int row = idx >> 2, quad = idx & 3;
            cpasync16(aB + (row * 40 + quad * 8) * 2,
                      A + (size_t)(rowBase + row) * lda + k0 + quad * 8,
                      (rowBase + row) < n);
            cpasync16(bB + (row * 40 + quad * 8) * 2,
                      B + (size_t)(colBase + row) * K + k0 + quad * 8, true);
        }
        asm volatile("cp.async.commit_group;");
    };

    auto compute = [&](int buf) {
        uint32_t aB = smem_u32(&As[buf][0]);
        uint32_t bB = smem_u32(&Bs[buf][0]);
#pragma unroll
        for (int ks = 0; ks < 2; ks++) {
            uint32_t af[4][4], bf[4][2];
            int arow = warpM * 64 + (lane & 15);
            int acol = ks * 16 + (lane >> 4) * 8;
#pragma unroll
            for (int mi = 0; mi < 4; mi++)
                ldmx4(af[mi][0], af[mi][1], af[mi][2], af[mi][3],
                      aB + ((arow + mi * 16) * 40 + acol) * 2);
#pragma unroll
            for (int np = 0; np < 2; np++) {
                int brow = warpN * 32 + np * 16 + (lane & 7) + ((lane >> 4) << 3);
                int bcol = ks * 16 + (((lane >> 3) & 1) << 3);
                ldmx4(bf[np * 2][0], bf[np * 2][1], bf[np * 2 + 1][0], bf[np * 2 + 1][1],
                      bB + (brow * 40 + bcol) * 2);
            }
#pragma unroll
            for (int mi = 0; mi < 4; mi++)
#pragma unroll
                for (int ni = 0; ni < 4; ni++) mma16816(acc[mi][ni], af[mi], bf[ni]);
        }
    };

    loadChunk(0, 0);
    for (int tc = 0; tc < total; tc++) {
        int buf = tc & 1;
        if (tc + 1 < total) {
            loadChunk(tc + 1, buf ^ 1);
            asm volatile("cp.async.wait_group 1;");
        } else {
            asm volatile("cp.async.wait_group 0;");
        }
        __syncthreads();
        compute(buf);
        __syncthreads();
    }
}

// ---------------- epilogues ----------------
__device__ __forceinline__ void epi_colmax(float acc[4][4][4], int n, int rBase, int cBase,
                                           int lane, const float* __restrict__ addvec,
                                           int* __restrict__ mv) {
    float cm[8];
#pragma unroll
    for (int j = 0; j < 8; j++) cm[j] = -1e30f;
#pragma unroll
    for (int mi = 0; mi < 4; mi++) {
        int r0 = rBase + mi * 16 + (lane >> 2);
        int r1 = r0 + 8;
#pragma unroll
        for (int ni = 0; ni < 4; ni++) {
            int col = cBase + ni * 8 + (lane & 3) * 2;
            float v0 = (r0 < n) ? tanhf(acc[mi][ni][0] + addvec[col]) : -1e30f;
            float v1 = (r0 < n) ? tanhf(acc[mi][ni][1] + addvec[col + 1]) : -1e30f;
            float v2 = (r1 < n) ? tanhf(acc[mi][ni][2] + addvec[col]) : -1e30f;
            float v3 = (r1 < n) ? tanhf(acc[mi][ni][3] + addvec[col + 1]) : -1e30f;
            cm[ni * 2] = fmaxf(cm[ni * 2], fmaxf(v0, v2));
            cm[ni * 2 + 1] = fmaxf(cm[ni * 2 + 1], fmaxf(v1, v3));
        }
    }
#pragma unroll
    for (int off = 4; off < 32; off <<= 1)
#pragma unroll
        for (int j = 0; j < 8; j++)
            cm[j] = fmaxf(cm[j], __shfl_xor_sync(0xffffffffu, cm[j], off));
    if (lane < 4) {
#pragma unroll
        for (int ni = 0; ni < 4; ni++) {
            int col = cBase + ni * 8 + lane * 2;
            atomicMax(&mv[col], __float_as_int(cm[ni * 2] + 2.0f));
            atomicMax(&mv[col + 1], __float_as_int(cm[ni * 2 + 1] + 2.0f));
        }
    }
}

// MODE 0: tanh(acc+addvec) -> half | MODE 1: acc+addvec -> half
template <int MODE>
__device__ __forceinline__ void epi_store_h(float acc[4][4][4], int n, int rBase, int cBase,
                                            int lane, const float* __restrict__ addvec,
                                            __half* __restrict__ outH, int ldO) {
#pragma unroll
    for (int mi = 0; mi < 4; mi++) {
#pragma unroll
        for (int h = 0; h < 2; h++) {
            int r = rBase + mi * 16 + (lane >> 2) + h * 8;
            if (r >= n) continue;
#pragma unroll
            for (int ni = 0; ni < 4; ni++) {
                int col = cBase + ni * 8 + (lane & 3) * 2;
                float v0 = acc[mi][ni][h * 2] + addvec[col];
                float v1 = acc[mi][ni][h * 2 + 1] + addvec[col + 1];
                if (MODE == 0) { v0 = tanhf(v0); v1 = tanhf(v1); }
                *(__half2*)(outH + (size_t)r * ldO + col) =
                    __halves2half2(__float2half_rn(v0), __float2half_rn(v1));
            }
        }
    }
}

// ---------------- GEMM 1 ----------------
__global__ __launch_bounds__(256)
void hmma_gemm1(const __half* __restrict__ A, int lda, const __half* __restrict__ B,
                int K, int n, __half* __restrict__ outH, int ldO,
                const float* __restrict__ addvec) {
    __shared__ __align__(16) __half As[2][128 * 40];
    __shared__ __align__(16) __half Bs[2][128 * 40];
    float acc[4][4][4];
#pragma unroll
    for (int a = 0; a < 4; a++)
#pragma unroll
        for (int b = 0; b < 4; b++)
#pragma unroll
            for (int c = 0; c < 4; c++) acc[a][b][c] = 0.0f;
    int rowBase = blockIdx.x * 128, colBase = blockIdx.y * 128;
    gemm_mainloop(A, lda, B, K, n, rowBase, colBase, As, Bs, acc);
    int lane = threadIdx.x & 31, warp = threadIdx.x >> 5;
    int rBase = rowBase + (warp & 1) * 64, cBase = colBase + (warp >> 1) * 32;
    epi_store_h<0>(acc, n, rBase, cBase, lane, addvec, outH, ldO);
}

// ---------------- GEMM 7 (cvec in-kernel) ----------------
__global__ __launch_bounds__(256)
void hmma_gemm7(const __half* __restrict__ A, int lda, const __half* __restrict__ B,
                int K, int n, __half* __restrict__ outH, int ldO,
                const int* __restrict__ mv, const float* __restrict__ W7) {
    __shared__ __align__(16) __half As[2][128 * 40];
    __shared__ __align__(16) __half Bs[2][128 * 40];
    __shared__ float sAdd[128];
    int tid = threadIdx.x;
    if (tid < 128) {
        float s = 0.0f;
        for (int k = 0; k < 256; k++)
            s += (__int_as_float(mv[k]) - 2.0f) * W7[(size_t)k * 128 + tid];
        sAdd[tid] = s;
    }
    float acc[4][4][4];
#pragma unroll
    for (int a = 0; a < 4; a++)
#pragma unroll
        for (int b = 0; b < 4; b++)
#pragma unroll
            for (int c = 0; c < 4; c++) acc[a][b][c] = 0.0f;
    int rowBase = blockIdx.x * 128;
    gemm_mainloop(A, lda, B, K, n, rowBase, 0, As, Bs, acc);
    int lane = tid & 31, warp = tid >> 5;
    int rBase = rowBase + (warp & 1) * 64, cBase = (warp >> 1) * 32;
    epi_store_h<1>(acc, n, rBase, cBase, lane, sAdd, outH, ldO);
}

// ---------------- merged U/V GEMM ----------------
__global__ __launch_bounds__(256)
void hmma_gemm_uv(const __half* __restrict__ agg1,
                  const __half* __restrict__ W2T, const __half* __restrict__ W4T,
                  int n, const float* __restrict__ b2, const float* __restrict__ b4,
                  __half* __restrict__ Vf, int* __restrict__ mv) {
    __shared__ __align__(16) __half As[2][128 * 40];
    __shared__ __align__(16) __half Bs[2][128 * 40];
    float acc[4][4][4];
#pragma unroll
    for (int a = 0; a < 4; a++)
#pragma unroll
        for (int b = 0; b < 4; b++)
#pragma unroll
            for (int c = 0; c < 4; c++) acc[a][b][c] = 0.0f;
    int z = blockIdx.z;
    const __half* A = agg1 + (z ? 128 : 0);
    const __half* B = z ? W4T : W2T;
    int rowBase = blockIdx.x * 128, colBase = blockIdx.y * 128;
    gemm_mainloop(A, 256, B, 128, n, rowBase, colBase, As, Bs, acc);
    int lane = threadIdx.x & 31, warp = threadIdx.x >> 5;
    int rBase = rowBase + (warp & 1) * 64, cBase = colBase + (warp >> 1) * 32;
    if (z == 0) {
        epi_colmax(acc, n, rBase, cBase, lane, b2, mv);
    } else {
        epi_store_h<0>(acc, n, rBase, cBase, lane, b4, Vf, 320);
    }
}

// ---------------- agg F=64 (1 warp/node) ----------------
__global__ void agg64_kernel(const __half* __restrict__ h, const int* __restrict__ rowptr,
                             const int* __restrict__ csrsrc, const float* __restrict__ csrnorm,
                             const float* __restrict__ dis, __half* __restrict__ out, int n) {
    int warp = (blockIdx.x * blockDim.x + threadIdx.x) >> 5;
    int lane = threadIdx.x & 31;
    if (warp >= n) return;
    float2 acc = make_float2(0.f, 0.f);
    int s0 = rowptr[warp], s1 = rowptr[warp + 1];
    int j = s0;
    for (; j + 1 < s1; j += 2) {
        int sa = csrsrc[j], sb = csrsrc[j + 1];
        float wa = csrnorm[j], wb = csrnorm[j + 1];
        float2 va = __half22float2(*(const __half2*)(h + (size_t)sa * 64 + lane * 2));
        float2 vb = __half22float2(*(const __half2*)(h + (size_t)sb * 64 + lane * 2));
        acc.x += va.x * wa + vb.x * wb;
        acc.y += va.y * wa + vb.y * wb;
    }
    if (j < s1) {
        int s = csrsrc[j];
        float w = csrnorm[j];
        float2 va = __half22float2(*(const __half2*)(h + (size_t)s * 64 + lane * 2));
        acc.x += va.x * w;
        acc.y += va.y * w;
    }
    float ds = dis[warp];
    float w2 = ds * ds;
    float2 v = __half22float2(*(const __half2*)(h + (size_t)warp * 64 + lane * 2));
    acc.x += v.x * w2;
    acc.y += v.y * w2;
    *(__half2*)(out + (size_t)warp * 64 + lane * 2) =
        __halves2half2(__float2half_rn(acc.x), __float2half_rn(acc.y));
}

// ---------------- agg F=256 (2 warps/node, smem combine) ----------------
__global__ void agg256_kernel(const __half* __restrict__ h, const int* __restrict__ rowptr,
                              const int* __restrict__ csrsrc, const float* __restrict__ csrnorm,
                              const float* __restrict__ dis, __half* __restrict__ out, int n) {
    __shared__ float sh[4][256];
    int tid = threadIdx.x;
    int lane = tid & 31, warp = tid >> 5;
    int nl = warp >> 1;                       // node slot 0..3
    int sub = warp & 1;
    int node = blockIdx.x * 4 + nl;
    int i0 = lane * 8;
    float acc[8] = {0.f, 0.f, 0.f, 0.f, 0.f, 0.f, 0.f, 0.f};

    if (node < n) {
        int s0 = rowptr[node], s1 = rowptr[node + 1];
        int half1 = (s1 - s0) >> 1;
        int js = sub ? (s0 + half1) : s0;
        int je = sub ? s1 : (s0 + half1);
        int j = js;
        for (; j + 1 < je; j += 2) {
            int sa = csrsrc[j], sb = csrsrc[j + 1];
            float wa = csrnorm[j], wb = csrnorm[j + 1];
            uint4 ra = *(const uint4*)(h + (size_t)sa * 256 + i0);
            uint4 rb = *(const uint4*)(h + (size_t)sb * 256 + i0);
            const __half2 *ha = (const __half2*)&ra, *hb = (const __half2*)&rb;
#pragma unroll
            for (int q = 0; q < 4; q++) {
                float2 fa = __half22float2(ha[q]);
                float2 fb = __half22float2(hb[q]);
                acc[q * 2] += fa.x * wa + fb.x * wb;
                acc[q * 2 + 1] += fa.y * wa + fb.y * wb;
            }
        }
        if (j < je) {
            int s = csrsrc[j];
            float w = csrnorm[j];
            uint4 raw = *(const uint4*)(h + (size_t)s * 256 + i0);
            const __half2* hp = (const __half2*)&raw;
#pragma unroll
            for (int q = 0; q < 4; q++) {
                float2 f = __half22float2(hp[q]);
                acc[q * 2] += f.x * w;
                acc[q * 2 + 1] += f.y * w;
            }
        }
        if (sub == 0) {  // self-loop
            float ds = dis[node];
            float w2 = ds * ds;
            uint4 raw = *(const uint4*)(h + (size_t)node * 256 + i0);
            const __half2* hp = (const __half2*)&raw;
#pragma unroll
            for (int q = 0; q < 4; q++) {
                float2 f = __half22float2(hp[q]);
                acc[q * 2] += f.x * w2;
                acc[q * 2 + 1] += f.y * w2;
            }
        }
    }
    if (sub == 1) {
        *(float4*)&sh[nl][i0] = make_float4(acc[0], acc[1], acc[2], acc[3]);
        *(float4*)&sh[nl][i0 + 4] = make_float4(acc[4], acc[5], acc[6], acc[7]);
    }
    __syncthreads();
    if (sub == 0 && node < n) {
        float4 p0 = *(const float4*)&sh[nl][i0];
        float4 p1 = *(const float4*)&sh[nl][i0 + 4];
        acc[0] += p0.x; acc[1] += p0.y; acc[2] += p0.z; acc[3] += p0.w;
        acc[4] += p1.x; acc[5] += p1.y; acc[6] += p1.z; acc[7] += p1.w;
        uint4 o;
        __half2* op = (__half2*)&o;
#pragma unroll
        for (int q = 0; q < 4; q++)
            op[q] = __halves2half2(__float2half_rn(acc[q * 2]), __float2half_rn(acc[q * 2 + 1]));
        *(uint4*)(out + (size_t)node * 256 + i0) = o;
    }
}

// ---------------- agg F=128 + bias + tanh (2 warps/node, smem combine) ----------------
__global__ void agg128t_kernel(const __half* __restrict__ h, const int* __restrict__ rowptr,
                               const int* __restrict__ csrsrc, const float* __restrict__ csrnorm,
                               const float* __restrict__ dis, const float* __restrict__ bias,
                               float* __restrict__ out, int n) {
    __shared__ float sh[4][128];
    int tid = threadIdx.x;
    int lane = tid & 31, warp = tid >> 5;
    int nl = warp >> 1;
    int sub = warp & 1;
    int node = blockIdx.x * 4 + nl;
    int idx = lane << 2;
    float4 acc = make_float4(0.f, 0.f, 0.f, 0.f);

    if (node < n) {
        int s0 = rowptr[node], s1 = rowptr[node + 1];
        int half1 = (s1 - s0) >> 1;
        int js = sub ? (s0 + half1) : s0;
        int je = sub ? s1 : (s0 + half1);
        int j = js;
        for (; j + 1 < je; j += 2) {
            int sa = csrsrc[j], sb = csrsrc[j + 1];
            float wa = csrnorm[j], wb = csrnorm[j + 1];
            uint2 ra = *(const uint2*)(h + (size_t)sa * 128 + idx);
            uint2 rb = *(const uint2*)(h + (size_t)sb * 128 + idx);
            float2 a0 = __half22float2(*(const __half2*)&ra.x);
            float2 a1 = __half22float2(*(const __half2*)&ra.y);
            float2 b0 = __half22float2(*(const __half2*)&rb.x);
            float2 b1 = __half22float2(*(const __half2*)&rb.y);
            acc.x += a0.x * wa + b0.x * wb;
            acc.y += a0.y * wa + b0.y * wb;
            acc.z += a1.x * wa + b1.x * wb;
            acc.w += a1.y * wa + b1.y * wb;
        }
        if (j < je) {
            int s = csrsrc[j];
            float w = csrnorm[j];
            uint2 ra = *(const uint2*)(h + (size_t)s * 128 + idx);
            float2 a0 = __half22float2(*(const __half2*)&ra.x);
            float2 a1 = __half22float2(*(const __half2*)&ra.y);
            acc.x += a0.x * w; acc.y += a0.y * w; acc.z += a1.x * w; acc.w += a1.y * w;
        }
        if (sub == 0) {  // self-loop
            float ds = dis[node];
            float w2 = ds * ds;
            uint2 rv = *(const uint2*)(h + (size_t)node * 128 + idx);
            float2 v0 = __half22float2(*(const __half2*)&rv.x);
            float2 v1 = __half22float2(*(const __half2*)&rv.y);
            acc.x += v0.x * w2; acc.y += v0.y * w2; acc.z += v1.x * w2; acc.w += v1.y * w2;
        }
    }
    if (sub == 1) *(float4*)&sh[nl][idx] = acc;
    __syncthreads();
    if (sub == 0 && node < n) {
        float4 p = *(const float4*)&sh[nl][idx];
        float4 bb = *(const float4*)(bias + idx);
        float4 r;
        r.x = tanhf(acc.x + p.x + bb.x);
        r.y = tanhf(acc.y + p.y + bb.y);
        r.z = tanhf(acc.z + p.z + bb.z);
        r.w = tanhf(acc.w + p.w + bb.w);
        *(float4*)(out + (size_t)node * 128 + idx) = r;
    }
}

extern "C" void kernel_launch(void* const* d_in, const int* in_sizes, int n_in,
                              void* d_out, int out_size) {
    const float* x = (const float*)d_in[0];
    const int* ei = (const int*)d_in[1];
    const float* W1 = (const float*)d_in[3];
    const float* b1 = (const float*)d_in[4];
    const float* W2 = (const float*)d_in[5];
    const float* b2 = (const float*)d_in[6];
    const float* W3 = (const float*)d_in[7];
    const float* b3 = (const float*)d_in[8];
    const float* W4 = (const float*)d_in[9];
    const float* b4 = (const float*)d_in[10];
    const float* W7 = (const float*)d_in[11];
    const float* b7 = (const float*)d_in[12];

    int n = in_sizes[0] / 64;
    int e = in_sizes[1] / 2;
    const int* src = ei;
    const int* dst = ei + e;
    float* out = (float*)d_out;

    __half *xh, *agg0, *T1, *agg1, *Vf, *H, *WcT, *W2T, *W4T, *W7T;
    float *dis, *csrnorm, *bc;
    int *cnt, *rowptr, *cursor, *csrsrc, *mv, *bsum;
    cudaGetSymbolAddress((void**)&xh, g_xh);
    cudaGetSymbolAddress((void**)&agg0, g_agg0);
    cudaGetSymbolAddress((void**)&T1, g_T1);
    cudaGetSymbolAddress((void**)&agg1, g_agg1);
    cudaGetSymbolAddress((void**)&Vf, g_Vf);
    cudaGetSymbolAddress((void**)&H, g_H);
    cudaGetSymbolAddress((void**)&dis, g_dis);
    cudaGetSymbolAddress((void**)&cnt, g_cnt);
    cudaGetSymbolAddress((void**)&rowptr, g_rowptr);
    cudaGetSymbolAddress((void**)&cursor, g_cursor);
    cudaGetSymbolAddress((void**)&csrsrc, g_csrsrc);
    cudaGetSymbolAddress((void**)&csrnorm, g_csrnorm);
    cudaGetSymbolAddress((void**)&bsum, g_bsum);
    cudaGetSymbolAddress((void**)&mv, g_mv);
    cudaGetSymbolAddress((void**)&WcT, g_WcT);
    cudaGetSymbolAddress((void**)&W2T, g_W2T);
    cudaGetSymbolAddress((void**)&W4T, g_W4T);
    cudaGetSymbolAddress((void**)&W7T, g_W7T);
    cudaGetSymbolAddress((void**)&bc, g_bc);

    int eb = (e + 255) / 256;
    int aggBlocks = (n + 7) / 8;       // agg64: 8 warps = 8 nodes/block
    int aggBlocks2 = (n + 3) / 4;      // split aggs: 8 warps = 4 nodes/block
    int gm = (n + 127) / 128;
    int nb = (n + 4095) / 4096;
    int convTotal = 122880 + n * 64;
    dim3 g2(gm, 2), guv(gm, 1, 2);

    // init + CSR build + conversions
    cudaMemsetAsync(cnt, 0, (size_t)n * sizeof(int));
    cudaMemsetAsync(bsum, 0, 64 * sizeof(int));
    cudaMemsetAsync(mv, 0, 256 * sizeof(int));
    conv_kernel<<<(convTotal + 255) / 256, 256>>>(W1, W3, W2, W4, W7, b1, b3, x,
                                                  WcT, W2T, W4T, W7T, bc, xh, Vf, n * 64);
    count_kernel<<<eb, 256>>>(dst, e, cnt);
    scan_fused_kernel<<<nb, 256>>>(cnt, n, bsum, rowptr, cursor, dis);
    fill_kernel<<<eb, 256>>>(src, dst, e, cursor, csrsrc, csrnorm, dis);

    // agg0 = P x
    agg64_kernel<<<aggBlocks, 256>>>(xh, rowptr, csrsrc, csrnorm, dis, agg0, n);
    // T1 = tanh(agg0 @ [W1|W3] + [b1|b3])
    hmma_gemm1<<<g2, 256>>>(agg0, 64, WcT, 64, n, T1, 256, bc);
    // agg1 = P T1 (2 warps/node)
    agg256_kernel<<<aggBlocks2, 256>>>(T1, rowptr, csrsrc, csrnorm, dis, agg1, n);
    // merged: z=0 colmax -> mv; z=1 V -> Vf
    hmma_gemm_uv<<<dim3(gm, 2, 2), 256>>>(agg1, W2T, W4T, n, b2, b4, Vf, mv);
    // H = [V|xh] @ W7T + cvec
    hmma_gemm7<<<gm, 256>>>(Vf, 320, W7T, 320, n, H, 128, mv, W7);
    // out = tanh(P H + b7)  (2 warps/node)
    agg128t_kernel<<<aggBlocks2, 256>>>(H, rowptr, csrsrc, csrnorm, dis, b7, out, n);
}

// round 13
// speedup vs baseline: 1.1100x; 1.1100x over previous
#include <cuda_runtime.h>
#include <cuda_fp16.h>
#include <math.h>
#include <stdint.h>

#define MAXN 50000
#define MAXE 400000

// ---------------- static scratch (all intermediates fp16) ----------------
__device__ __half g_xh[MAXN * 64];
__device__ __half g_agg0[MAXN * 64];
__device__ __half g_T1[MAXN * 256];
__device__ __half g_agg1[MAXN * 256];
__device__ __half g_Vf[MAXN * 320];      // V (0:256) | xh (256:320)
__device__ __half g_H[MAXN * 128];
__device__ float g_dis[MAXN];
__device__ int g_cnt[MAXN], g_rowptr[MAXN + 1], g_csrsrc[MAXE];
__device__ int g_eoff[MAXE];             // within-node rank of each input edge
__device__ float g_csrnorm[MAXE];
__device__ int g_bsum[64];
__device__ int g_mv[256];
__device__ __half g_WcT[256 * 64];
__device__ __half g_W2T[256 * 128];
__device__ __half g_W4T[256 * 128];
__device__ __half g_W7T[128 * 320];
__device__ float g_bc[256];

// ---------------- helpers ----------------
__device__ __forceinline__ uint32_t smem_u32(const void* p) {
    uint32_t a;
    asm("{ .reg .u64 t; cvta.to.shared.u64 t, %1; cvt.u32.u64 %0, t; }" : "=r"(a) : "l"(p));
    return a;
}
__device__ __forceinline__ void cpasync16(uint32_t dst, const void* src, bool pred) {
    int sz = pred ? 16 : 0;
    asm volatile("cp.async.cg.shared.global [%0], [%1], 16, %2;\n" :: "r"(dst), "l"(src), "r"(sz));
}
__device__ __forceinline__ void ldmx4(uint32_t& r0, uint32_t& r1, uint32_t& r2, uint32_t& r3,
                                      uint32_t addr) {
    asm volatile("ldmatrix.sync.aligned.m8n8.x4.shared.b16 {%0,%1,%2,%3}, [%4];"
                 : "=r"(r0), "=r"(r1), "=r"(r2), "=r"(r3) : "r"(addr));
}
__device__ __forceinline__ void mma16816(float* c, const uint32_t* a, const uint32_t* b) {
    asm volatile(
        "mma.sync.aligned.m16n8k16.row.col.f32.f16.f16.f32 "
        "{%0,%1,%2,%3}, {%4,%5,%6,%7}, {%8,%9}, {%0,%1,%2,%3};"
        : "+f"(c[0]), "+f"(c[1]), "+f"(c[2]), "+f"(c[3])
        : "r"(a[0]), "r"(a[1]), "r"(a[2]), "r"(a[3]), "r"(b[0]), "r"(b[1]));
}

// ---------------- merged conversion + degree count (independent phases) ----------------
__global__ void conv_count_kernel(const float* __restrict__ W1, const float* __restrict__ W3,
                                  const float* __restrict__ W2, const float* __restrict__ W4,
                                  const float* __restrict__ W7, const float* __restrict__ b1,
                                  const float* __restrict__ b3, const float* __restrict__ x,
                                  __half* WcT, __half* W2T, __half* W4T, __half* W7T,
                                  float* bc, __half* xh, __half* Vf, int xtotal,
                                  const int* __restrict__ dst, int e,
                                  int* __restrict__ cnt, int* __restrict__ eoff) {
    int i = blockIdx.x * blockDim.x + threadIdx.x;
    int convTotal = 122880 + xtotal;
    if (i < 256) bc[i] = (i < 128) ? b1[i] : b3[i - 128];
    if (i < 122880) {  // weights
        float v;
        __half* o;
        int off;
        if (i < 16384) {
            int c = i >> 6, k = i & 63;
            v = (c < 128) ? W1[k * 128 + c] : W3[k * 128 + (c - 128)];
            o = WcT; off = i;
        } else if (i < 49152) {
            int j = i - 16384; int c = j >> 7, k = j & 127;
            v = W2[k * 256 + c]; o = W2T; off = j;
        } else if (i < 81920) {
            int j = i - 49152; int c = j >> 7, k = j & 127;
            v = W4[k * 256 + c]; o = W4T; off = j;
        } else {
            int j = i - 81920; int c = j / 320, k = j % 320;
            v = (k < 256) ? W7[(size_t)(256 + k) * 128 + c]
                          : W7[(size_t)(512 + (k - 256)) * 128 + c];
            o = W7T; off = j;
        }
        o[off] = __float2half_rn(v);
    } else if (i < convTotal) {  // x conversion
        int j = i - 122880;
        int row = j >> 6, c = j & 63;
        __half h = __float2half_rn(x[j]);
        xh[j] = h;
        Vf[(size_t)row * 320 + 256 + c] = h;
    } else {  // degree count + within-node rank
        int j = i - convTotal;
        if (j < e) eoff[j] = atomicAdd(&cnt[dst[j]], 1);
    }
}

// ---------------- fused scan (13 blocks, sentinel lookback) ----------------
__global__ void scan_fused_kernel(const int* __restrict__ cnt, int n, int* __restrict__ bsum,
                                  int* __restrict__ rowptr, float* __restrict__ dis) {
    int tid = threadIdx.x;
    int lane = tid & 31, warp = tid >> 5;
    int base = (blockIdx.x * 256 + tid) * 16;
    int vals[16];
    int s = 0;
#pragma unroll
    for (int i = 0; i < 16; i++) {
        int idx = base + i;
        vals[i] = (idx < n) ? cnt[idx] : 0;
        s += vals[i];
    }
    int incl = s;
#pragma unroll
    for (int o = 1; o < 32; o <<= 1) {
        int t = __shfl_up_sync(0xffffffffu, incl, o);
        if (lane >= o) incl += t;
    }
    __shared__ int wsum[8];
    if (lane == 31) wsum[warp] = incl;
    __syncthreads();
    int woff = 0, total = 0;
#pragma unroll
    for (int w = 0; w < 8; w++) {
        if (w < warp) woff += wsum[w];
        total += wsum[w];
    }
    __shared__ int sPre;
    if (tid == 0) {
        atomicExch(&bsum[blockIdx.x], total + 1);
        int pre = 0;
        for (int w = 0; w < (int)blockIdx.x; w++) {
            int v;
            do { v = atomicAdd(&bsum[w], 0); } while (v == 0);
            pre += v - 1;
        }
        sPre = pre;
    }
    __syncthreads();
    int excl = sPre + woff + (incl - s);
#pragma unroll
    for (int i = 0; i < 16; i++) {
        int idx = base + i;
        if (idx < n) {
            rowptr[idx] = excl;
            dis[idx] = rsqrtf((float)(vals[i] + 1));
            excl += vals[i];
        }
    }
    if (blockIdx.x == gridDim.x - 1 && tid == 0) rowptr[n] = sPre + total;
}

// ---------------- CSR fill (atomic-free: slot = rowptr[d] + eoff[i]) ----------------
__global__ void fill_kernel(const int* __restrict__ src, const int* __restrict__ dst, int e,
                            const int* __restrict__ rowptr, const int* __restrict__ eoff,
                            int* __restrict__ csrsrc, float* __restrict__ csrnorm,
                            const float* __restrict__ dis) {
    int i = blockIdx.x * blockDim.x + threadIdx.x;
    if (i >= e) return;
    int d = dst[i], s = src[i];
    int p = rowptr[d] + eoff[i];
    csrsrc[p] = s;
    csrnorm[p] = dis[s] * dis[d];
}

// ---------------- HMMA mainloop (pure fp16, 128x128x32) ----------------
__device__ __forceinline__ void gemm_mainloop(
    const __half* __restrict__ A, int lda,
    const __half* __restrict__ B,
    int K, int n, int rowBase, int colBase,
    __half (*As)[128 * 40], __half (*Bs)[128 * 40],
    float acc[4][4][4]) {
    int tid = threadIdx.x;
    int lane = tid & 31, warp = tid >> 5;
    int warpM = warp & 1, warpN = warp >> 1;
    int total = K >> 5;

    auto loadChunk = [&](int kc, int buf) {
        int k0 = kc << 5;
        uint32_t aB = smem_u32(&As[buf][0]);
        uint32_t bB = smem_u32(&Bs[buf][0]);
#pragma unroll
        for (int i = 0; i < 2; i++) {
            int idx = tid + (i << 8);
            int row = idx >> 2, quad = idx & 3;
            cpasync16(aB + (row * 40 + quad * 8) * 2,
                      A + (size_t)(rowBase + row) * lda + k0 + quad * 8,
                      (rowBase + row) < n);
            cpasync16(bB + (row * 40 + quad * 8) * 2,
                      B + (size_t)(colBase + row) * K + k0 + quad * 8, true);
        }
        asm volatile("cp.async.commit_group;");
    };

    auto compute = [&](int buf) {
        uint32_t aB = smem_u32(&As[buf][0]);
        uint32_t bB = smem_u32(&Bs[buf][0]);
#pragma unroll
        for (int ks = 0; ks < 2; ks++) {
            uint32_t af[4][4], bf[4][2];
            int arow = warpM * 64 + (lane & 15);
            int acol = ks * 16 + (lane >> 4) * 8;
#pragma unroll
            for (int mi = 0; mi < 4; mi++)
                ldmx4(af[mi][0], af[mi][1], af[mi][2], af[mi][3],
                      aB + ((arow + mi * 16) * 40 + acol) * 2);
#pragma unroll
            for (int np = 0; np < 2; np++) {
                int brow = warpN * 32 + np * 16 + (lane & 7) + ((lane >> 4) << 3);
                int bcol = ks * 16 + (((lane >> 3) & 1) << 3);
                ldmx4(bf[np * 2][0], bf[np * 2][1], bf[np * 2 + 1][0], bf[np * 2 + 1][1],
                      bB + (brow * 40 + bcol) * 2);
            }
#pragma unroll
            for (int mi = 0; mi < 4; mi++)
#pragma unroll
                for (int ni = 0; ni < 4; ni++) mma16816(acc[mi][ni], af[mi], bf[ni]);
        }
    };

    loadChunk(0, 0);
    for (int tc = 0; tc < total; tc++) {
        int buf = tc & 1;
        if (tc + 1 < total) {
            loadChunk(tc + 1, buf ^ 1);
            asm volatile("cp.async.wait_group 1;");
        } else {
            asm volatile("cp.async.wait_group 0;");
        }
        __syncthreads();
        compute(buf);
        __syncthreads();
    }
}

// ---------------- epilogues ----------------
__device__ __forceinline__ void epi_colmax(float acc[4][4][4], int n, int rBase, int cBase,
                                           int lane, const float* __restrict__ addvec,
                                           int* __restrict__ mv) {
    float cm[8];
#pragma unroll
    for (int j = 0; j < 8; j++) cm[j] = -1e30f;
#pragma unroll
    for (int mi = 0; mi < 4; mi++) {
        int r0 = rBase + mi * 16 + (lane >> 2);
        int r1 = r0 + 8;
#pragma unroll
        for (int ni = 0; ni < 4; ni++) {
            int col = cBase + ni * 8 + (lane & 3) * 2;
            float v0 = (r0 < n) ? tanhf(acc[mi][ni][0] + addvec[col]) : -1e30f;
            float v1 = (r0 < n) ? tanhf(acc[mi][ni][1] + addvec[col + 1]) : -1e30f;
            float v2 = (r1 < n) ? tanhf(acc[mi][ni][2] + addvec[col]) : -1e30f;
            float v3 = (r1 < n) ? tanhf(acc[mi][ni][3] + addvec[col + 1]) : -1e30f;
            cm[ni * 2] = fmaxf(cm[ni * 2], fmaxf(v0, v2));
            cm[ni * 2 + 1] = fmaxf(cm[ni * 2 + 1], fmaxf(v1, v3));
        }
    }
#pragma unroll
    for (int off = 4; off < 32; off <<= 1)
#pragma unroll
        for (int j = 0; j < 8; j++)
            cm[j] = fmaxf(cm[j], __shfl_xor_sync(0xffffffffu, cm[j], off));
    if (lane < 4) {
#pragma unroll
        for (int ni = 0; ni < 4; ni++) {
            int col = cBase + ni * 8 + lane * 2;
            atomicMax(&mv[col], __float_as_int(cm[ni * 2] + 2.0f));
            atomicMax(&mv[col + 1], __float_as_int(cm[ni * 2 + 1] + 2.0f));
        }
    }
}

// MODE 0: tanh(acc+addvec) -> half | MODE 1: acc+addvec -> half
template <int MODE>
__device__ __forceinline__ void epi_store_h(float acc[4][4][4], int n, int rBase, int cBase,
                                            int lane, const float* __restrict__ addvec,
                                            __half* __restrict__ outH, int ldO) {
#pragma unroll
    for (int mi = 0; mi < 4; mi++) {
#pragma unroll
        for (int h = 0; h < 2; h++) {
            int r = rBase + mi * 16 + (lane >> 2) + h * 8;
            if (r >= n) continue;
#pragma unroll
            for (int ni = 0; ni < 4; ni++) {
                int col = cBase + ni * 8 + (lane & 3) * 2;
                float v0 = acc[mi][ni][h * 2] + addvec[col];
                float v1 = acc[mi][ni][h * 2 + 1] + addvec[col + 1];
                if (MODE == 0) { v0 = tanhf(v0); v1 = tanhf(v1); }
                *(__half2*)(outH + (size_t)r * ldO + col) =
                    __halves2half2(__float2half_rn(v0), __float2half_rn(v1));
            }
        }
    }
}

// ---------------- GEMM 1 ----------------
__global__ __launch_bounds__(256)
void hmma_gemm1(const __half* __restrict__ A, int lda, const __half* __restrict__ B,
                int K, int n, __half* __restrict__ outH, int ldO,
                const float* __restrict__ addvec) {
    __shared__ __align__(16) __half As[2][128 * 40];
    __shared__ __align__(16) __half Bs[2][128 * 40];
    float acc[4][4][4];
#pragma unroll
    for (int a = 0; a < 4; a++)
#pragma unroll
        for (int b = 0; b < 4; b++)
#pragma unroll
            for (int c = 0; c < 4; c++) acc[a][b][c] = 0.0f;
    int rowBase = blockIdx.x * 128, colBase = blockIdx.y * 128;
    gemm_mainloop(A, lda, B, K, n, rowBase, colBase, As, Bs, acc);
    int lane = threadIdx.x & 31, warp = threadIdx.x >> 5;
    int rBase = rowBase + (warp & 1) * 64, cBase = colBase + (warp >> 1) * 32;
    epi_store_h<0>(acc, n, rBase, cBase, lane, addvec, outH, ldO);
}

// ---------------- GEMM 7 (cvec in-kernel) ----------------
__global__ __launch_bounds__(256)
void hmma_gemm7(const __half* __restrict__ A, int lda, const __half* __restrict__ B,
                int K, int n, __half* __restrict__ outH, int ldO,
                const int* __restrict__ mv, const float* __restrict__ W7) {
    __shared__ __align__(16) __half As[2][128 * 40];
    __shared__ __align__(16) __half Bs[2][128 * 40];
    __shared__ float sAdd[128];
    int tid = threadIdx.x;
    if (tid < 128) {
        float s = 0.0f;
        for (int k = 0; k < 256; k++)
            s += (__int_as_float(mv[k]) - 2.0f) * W7[(size_t)k * 128 + tid];
        sAdd[tid] = s;
    }
    float acc[4][4][4];
#pragma unroll
    for (int a = 0; a < 4; a++)
#pragma unroll
        for (int b = 0; b < 4; b++)
#pragma unroll
            for (int c = 0; c < 4; c++) acc[a][b][c] = 0.0f;
    int rowBase = blockIdx.x * 128;
    gemm_mainloop(A, lda, B, K, n, rowBase, 0, As, Bs, acc);
    int lane = tid & 31, warp = tid >> 5;
    int rBase = rowBase + (warp & 1) * 64, cBase = (warp >> 1) * 32;
    epi_store_h<1>(acc, n, rBase, cBase, lane, sAdd, outH, ldO);
}

// ---------------- merged U/V GEMM (z=0: colmax; z=1: V -> half) ----------------
__global__ __launch_bounds__(256)
void hmma_gemm_uv(const __half* __restrict__ agg1,
                  const __half* __restrict__ W2T, const __half* __restrict__ W4T,
                  int n, const float* __restrict__ b2, const float* __restrict__ b4,
                  __half* __restrict__ Vf, int* __restrict__ mv) {
    __shared__ __align__(16) __half As[2][128 * 40];
    __shared__ __align__(16) __half Bs[2][128 * 40];
    float acc[4][4][4];
#pragma unroll
    for (int a = 0; a < 4; a++)
#pragma unroll
        for (int b = 0; b < 4; b++)
#pragma unroll
            for (int c = 0; c < 4; c++) acc[a][b][c] = 0.0f;
    int z = blockIdx.z;
    const __half* A = agg1 + (z ? 128 : 0);
    const __half* B = z ? W4T : W2T;
    int rowBase = blockIdx.x * 128, colBase = blockIdx.y * 128;
    gemm_mainloop(A, 256, B, 128, n, rowBase, colBase, As, Bs, acc);
    int lane = threadIdx.x & 31, warp = threadIdx.x >> 5;
    int rBase = rowBase + (warp & 1) * 64, cBase = colBase + (warp >> 1) * 32;
    if (z == 0) {
        epi_colmax(acc, n, rBase, cBase, lane, b2, mv);
    } else {
        epi_store_h<0>(acc, n, rBase, cBase, lane, b4, Vf, 320);
    }
}

// ---------------- agg F=64 ----------------
__global__ void agg64_kernel(const __half* __restrict__ h, const int* __restrict__ rowptr,
                             const int* __restrict__ csrsrc, const float* __restrict__ csrnorm,
                             const float* __restrict__ dis, __half* __restrict__ out, int n) {
    int warp = (blockIdx.x * blockDim.x + threadIdx.x) >> 5;
    int lane = threadIdx.x & 31;
    if (warp >= n) return;
    float2 acc = make_float2(0.f, 0.f);
    int s0 = rowptr[warp], s1 = rowptr[warp + 1];
    int j = s0;
    for (; j + 1 < s1; j += 2) {
        int sa = csrsrc[j], sb = csrsrc[j + 1];
        float wa = csrnorm[j], wb = csrnorm[j + 1];
        float2 va = __half22float2(*(const __half2*)(h + (size_t)sa * 64 + lane * 2));
        float2 vb = __half22float2(*(const __half2*)(h + (size_t)sb * 64 + lane * 2));
        acc.x += va.x * wa + vb.x * wb;
        acc.y += va.y * wa + vb.y * wb;
    }
    if (j < s1) {
        int s = csrsrc[j];
        float w = csrnorm[j];
        float2 va = __half22float2(*(const __half2*)(h + (size_t)s * 64 + lane * 2));
        acc.x += va.x * w;
        acc.y += va.y * w;
    }
    float ds = dis[warp];
    float w2 = ds * ds;
    float2 v = __half22float2(*(const __half2*)(h + (size_t)warp * 64 + lane * 2));
    acc.x += v.x * w2;
    acc.y += v.y * w2;
    *(__half2*)(out + (size_t)warp * 64 + lane * 2) =
        __halves2half2(__float2half_rn(acc.x), __float2half_rn(acc.y));
}

// ---------------- agg F=256 (edge-unrolled x4) ----------------
__global__ void agg256_kernel(const __half* __restrict__ h, const int* __restrict__ rowptr,
                              const int* __restrict__ csrsrc, const float* __restrict__ csrnorm,
                              const float* __restrict__ dis, __half* __restrict__ out, int n) {
    int warp = (blockIdx.x * blockDim.x + threadIdx.x) >> 5;
    int lane = threadIdx.x & 31;
    if (warp >= n) return;
    float acc[8] = {0.f, 0.f, 0.f, 0.f, 0.f, 0.f, 0.f, 0.f};
    int s0 = rowptr[warp], s1 = rowptr[warp + 1];
    int i0 = lane * 8;
    int j = s0;
    for (; j + 3 < s1; j += 4) {
        int sa = csrsrc[j], sb = csrsrc[j + 1], sc = csrsrc[j + 2], sd = csrsrc[j + 3];
        float wa = csrnorm[j], wb = csrnorm[j + 1], wc = csrnorm[j + 2], wd = csrnorm[j + 3];
        uint4 ra = *(const uint4*)(h + (size_t)sa * 256 + i0);
        uint4 rb = *(const uint4*)(h + (size_t)sb * 256 + i0);
        uint4 rc = *(const uint4*)(h + (size_t)sc * 256 + i0);
        uint4 rd = *(const uint4*)(h + (size_t)sd * 256 + i0);
        const __half2 *ha = (const __half2*)&ra, *hb = (const __half2*)&rb;
        const __half2 *hc = (const __half2*)&rc, *hd = (const __half2*)&rd;
#pragma unroll
        for (int q = 0; q < 4; q++) {
            float2 fa = __half22float2(ha[q]);
            float2 fb = __half22float2(hb[q]);
            float2 fc = __half22float2(hc[q]);
            float2 fd = __half22float2(hd[q]);
            acc[q * 2] += fa.x * wa + fb.x * wb + fc.x * wc + fd.x * wd;
            acc[q * 2 + 1] += fa.y * wa + fb.y * wb + fc.y * wc + fd.y * wd;
        }
    }
    for (; j < s1; j++) {
        int s = csrsrc[j];
        float w = csrnorm[j];
        uint4 raw = *(const uint4*)(h + (size_t)s * 256 + i0);
        const __half2* hp = (const __half2*)&raw;
#pragma unroll
        for (int q = 0; q < 4; q++) {
            float2 f = __half22float2(hp[q]);
            acc[q * 2] += f.x * w;
            acc[q * 2 + 1] += f.y * w;
        }
    }
    float ds = dis[warp];
    float w2 = ds * ds;
    uint4 raw = *(const uint4*)(h + (size_t)warp * 256 + i0);
    const __half2* hp = (const __half2*)&raw;
#pragma unroll
    for (int q = 0; q < 4; q++) {
        float2 f = __half22float2(hp[q]);
        acc[q * 2] += f.x * w2;
        acc[q * 2 + 1] += f.y * w2;
    }
    uint4 o;
    __half2* op = (__half2*)&o;
#pragma unroll
    for (int q = 0; q < 4; q++)
        op[q] = __halves2half2(__float2half_rn(acc[q * 2]), __float2half_rn(acc[q * 2 + 1]));
    *(uint4*)(out + (size_t)warp * 256 + i0) = o;
}

// ---------------- agg F=128 + bias + tanh (final, fp32 out) ----------------
__global__ void agg128t_kernel(const __half* __restrict__ h, const int* __restrict__ rowptr,
                               const int* __restrict__ csrsrc, const float* __restrict__ csrnorm,
                               const float* __restrict__ dis, const float* __restrict__ bias,
                               float* __restrict__ out, int n) {
    int warp = (blockIdx.x * blockDim.x + threadIdx.x) >> 5;
    int lane = threadIdx.x & 31;
    if (warp >= n) return;
    float4 acc = make_float4(0.f, 0.f, 0.f, 0.f);
    int s0 = rowptr[warp], s1 = rowptr[warp + 1];
    int idx = lane << 2;
    int j = s0;
    for (; j + 1 < s1; j += 2) {
        int sa = csrsrc[j], sb = csrsrc[j + 1];
        float wa = csrnorm[j], wb = csrnorm[j + 1];
        uint2 ra = *(const uint2*)(h + (size_t)sa * 128 + idx);
        uint2 rb = *(const uint2*)(h + (size_t)sb * 128 + idx);
        float2 a0 = __half22float2(*(const __half2*)&ra.x);
        float2 a1 = __half22float2(*(const __half2*)&ra.y);
        float2 b0 = __half22float2(*(const __half2*)&rb.x);
        float2 b1 = __half22float2(*(const __half2*)&rb.y);
        acc.x += a0.x * wa + b0.x * wb;
        acc.y += a0.y * wa + b0.y * wb;
        acc.z += a1.x * wa + b1.x * wb;
        acc.w += a1.y * wa + b1.y * wb;
    }
    if (j < s1) {
        int s = csrsrc[j];
        float w = csrnorm[j];
        uint2 ra = *(const uint2*)(h + (size_t)s * 128 + idx);
        float2 a0 = __half22float2(*(const __half2*)&ra.x);
        float2 a1 = __half22float2(*(const __half2*)&ra.y);
        acc.x += a0.x * w; acc.y += a0.y * w; acc.z += a1.x * w; acc.w += a1.y * w;
    }
    float ds = dis[warp];
    float w2 = ds * ds;
    uint2 rv = *(const uint2*)(h + (size_t)warp * 128 + idx);
    float2 v0 = __half22float2(*(const __half2*)&rv.x);
    float2 v1 = __half22float2(*(const __half2*)&rv.y);
    float4 bb = *(const float4*)(bias + idx);
    float4 r;
    r.x = tanhf(acc.x + v0.x * w2 + bb.x);
    r.y = tanhf(acc.y + v0.y * w2 + bb.y);
    r.z = tanhf(acc.z + v1.x * w2 + bb.z);
    r.w = tanhf(acc.w + v1.y * w2 + bb.w);
    *(float4*)(out + (size_t)warp * 128 + idx) = r;
}

extern "C" void kernel_launch(void* const* d_in, const int* in_sizes, int n_in,
                              void* d_out, int out_size) {
    const float* x = (const float*)d_in[0];
    const int* ei = (const int*)d_in[1];
    const float* W1 = (const float*)d_in[3];
    const float* b1 = (const float*)d_in[4];
    const float* W2 = (const float*)d_in[5];
    const float* b2 = (const float*)d_in[6];
    const float* W3 = (const float*)d_in[7];
    const float* b3 = (const float*)d_in[8];
    const float* W4 = (const float*)d_in[9];
    const float* b4 = (const float*)d_in[10];
    const float* W7 = (const float*)d_in[11];
    const float* b7 = (const float*)d_in[12];

    int n = in_sizes[0] / 64;
    int e = in_sizes[1] / 2;
    const int* src = ei;
    const int* dst = ei + e;
    float* out = (float*)d_out;

    __half *xh, *agg0, *T1, *agg1, *Vf, *H, *WcT, *W2T, *W4T, *W7T;
    float *dis, *csrnorm, *bc;
    int *cnt, *rowptr, *csrsrc, *eoff, *mv, *bsum;
    cudaGetSymbolAddress((void**)&xh, g_xh);
    cudaGetSymbolAddress((void**)&agg0, g_agg0);
    cudaGetSymbolAddress((void**)&T1, g_T1);
    cudaGetSymbolAddress((void**)&agg1, g_agg1);
    cudaGetSymbolAddress((void**)&Vf, g_Vf);
    cudaGetSymbolAddress((void**)&H, g_H);
    cudaGetSymbolAddress((void**)&dis, g_dis);
    cudaGetSymbolAddress((void**)&cnt, g_cnt);
    cudaGetSymbolAddress((void**)&rowptr, g_rowptr);
    cudaGetSymbolAddress((void**)&csrsrc, g_csrsrc);
    cudaGetSymbolAddress((void**)&eoff, g_eoff);
    cudaGetSymbolAddress((void**)&csrnorm, g_csrnorm);
    cudaGetSymbolAddress((void**)&bsum, g_bsum);
    cudaGetSymbolAddress((void**)&mv, g_mv);
    cudaGetSymbolAddress((void**)&WcT, g_WcT);
    cudaGetSymbolAddress((void**)&W2T, g_W2T);
    cudaGetSymbolAddress((void**)&W4T, g_W4T);
    cudaGetSymbolAddress((void**)&W7T, g_W7T);
    cudaGetSymbolAddress((void**)&bc, g_bc);

    int eb = (e + 255) / 256;
    int aggBlocks = (n + 7) / 8;
    int gm = (n + 127) / 128;
    int nb = (n + 4095) / 4096;
    int mergedTotal = 122880 + n * 64 + e;
    dim3 g2(gm, 2), guv(gm, 2, 2);

    // init + merged conversions/count + scan + atomic-free fill
    cudaMemsetAsync(cnt, 0, (size_t)n * sizeof(int));
    cudaMemsetAsync(bsum, 0, 64 * sizeof(int));
    cudaMemsetAsync(mv, 0, 256 * sizeof(int));
    conv_count_kernel<<<(mergedTotal + 255) / 256, 256>>>(
        W1, W3, W2, W4, W7, b1, b3, x, WcT, W2T, W4T, W7T, bc, xh, Vf, n * 64,
        dst, e, cnt, eoff);
    scan_fused_kernel<<<nb, 256>>>(cnt, n, bsum, rowptr, dis);
    fill_kernel<<<eb, 256>>>(src, dst, e, rowptr, eoff, csrsrc, csrnorm, dis);

    // agg0 = P x
    agg64_kernel<<<aggBlocks, 256>>>(xh, rowptr, csrsrc, csrnorm, dis, agg0, n);
    // T1 = tanh(agg0 @ [W1|W3] + [b1|b3])
    hmma_gemm1<<<g2, 256>>>(agg0, 64, WcT, 64, n, T1, 256, bc);
    // agg1 = P T1
    agg256_kernel<<<aggBlocks, 256>>>(T1, rowptr, csrsrc, csrnorm, dis, agg1, n);
    // merged: z=0 colmax -> mv; z=1 V -> Vf
    hmma_gemm_uv<<<guv, 256>>>(agg1, W2T, W4T, n, b2, b4, Vf, mv);
    // H = [V|xh] @ W7T + cvec
    hmma_gemm7<<<gm, 256>>>(Vf, 320, W7T, 320, n, H, 128, mv, W7);
    // out = tanh(P H + b7)
    agg128t_kernel<<<aggBlocks, 256>>>(H, rowptr, csrsrc, csrnorm, dis, b7, out, n);
}

// round 14
// speedup vs baseline: 1.1326x; 1.0204x over previous
#include <cuda_runtime.h>
#include <cuda_fp16.h>
#include <math.h>
#include <stdint.h>

#define MAXN 50000
#define MAXE 400000

// ---------------- static scratch (all intermediates fp16) ----------------
__device__ __half g_xh[MAXN * 64];
__device__ __half g_agg0[MAXN * 64];
__device__ __half g_T1[MAXN * 256];
__device__ __half g_agg1[MAXN * 256];
__device__ __half g_Vf[MAXN * 320];      // V (0:256) | xh (256:320)
__device__ __half g_H[MAXN * 128];
__device__ float g_dis[MAXN];
__device__ int g_cnt[MAXN], g_rowptr[MAXN + 1], g_csrsrc[MAXE];
__device__ int g_eoff[MAXE];             // within-node rank of each input edge
__device__ float g_csrnorm[MAXE];
__device__ int g_bsum[64];
__device__ int g_mv[256];
__device__ __half g_WcT[256 * 64];
__device__ __half g_W2T[256 * 128];
__device__ __half g_W4T[256 * 128];
__device__ __half g_W7T[128 * 320];
__device__ float g_bc[256];

// ---------------- helpers ----------------
__device__ __forceinline__ uint32_t smem_u32(const void* p) {
    uint32_t a;
    asm("{ .reg .u64 t; cvta.to.shared.u64 t, %1; cvt.u32.u64 %0, t; }" : "=r"(a) : "l"(p));
    return a;
}
__device__ __forceinline__ void cpasync16(uint32_t dst, const void* src, bool pred) {
    int sz = pred ? 16 : 0;
    asm volatile("cp.async.cg.shared.global [%0], [%1], 16, %2;\n" :: "r"(dst), "l"(src), "r"(sz));
}
__device__ __forceinline__ void ldmx4(uint32_t& r0, uint32_t& r1, uint32_t& r2, uint32_t& r3,
                                      uint32_t addr) {
    asm volatile("ldmatrix.sync.aligned.m8n8.x4.shared.b16 {%0,%1,%2,%3}, [%4];"
                 : "=r"(r0), "=r"(r1), "=r"(r2), "=r"(r3) : "r"(addr));
}
__device__ __forceinline__ void mma16816(float* c, const uint32_t* a, const uint32_t* b) {
    asm volatile(
        "mma.sync.aligned.m16n8k16.row.col.f32.f16.f16.f32 "
        "{%0,%1,%2,%3}, {%4,%5,%6,%7}, {%8,%9}, {%0,%1,%2,%3};"
        : "+f"(c[0]), "+f"(c[1]), "+f"(c[2]), "+f"(c[3])
        : "r"(a[0]), "r"(a[1]), "r"(a[2]), "r"(a[3]), "r"(b[0]), "r"(b[1]));
}

// ---------------- merged conversion + degree count + scratch zeroing ----------------
__global__ void conv_count_kernel(const float* __restrict__ W1, const float* __restrict__ W3,
                                  const float* __restrict__ W2, const float* __restrict__ W4,
                                  const float* __restrict__ W7, const float* __restrict__ b1,
                                  const float* __restrict__ b3, const float* __restrict__ x,
                                  __half* WcT, __half* W2T, __half* W4T, __half* W7T,
                                  float* bc, __half* xh, __half* Vf, int xtotal,
                                  const int* __restrict__ dst, int e,
                                  int* __restrict__ cnt, int* __restrict__ eoff,
                                  int* __restrict__ bsum, int* __restrict__ mv) {
    int i = blockIdx.x * blockDim.x + threadIdx.x;
    int convTotal = 122880 + xtotal;
    if (i < 256) {
        bc[i] = (i < 128) ? b1[i] : b3[i - 128];
        mv[i] = 0;
        if (i < 64) bsum[i] = 0;
    }
    if (i < 122880) {  // weights
        float v;
        __half* o;
        int off;
        if (i < 16384) {
            int c = i >> 6, k = i & 63;
            v = (c < 128) ? W1[k * 128 + c] : W3[k * 128 + (c - 128)];
            o = WcT; off = i;
        } else if (i < 49152) {
            int j = i - 16384; int c = j >> 7, k = j & 127;
            v = W2[k * 256 + c]; o = W2T; off = j;
        } else if (i < 81920) {
            int j = i - 49152; int c = j >> 7, k = j & 127;
            v = W4[k * 256 + c]; o = W4T; off = j;
        } else {
            int j = i - 81920; int c = j / 320, k = j % 320;
            v = (k < 256) ? W7[(size_t)(256 + k) * 128 + c]
                          : W7[(size_t)(512 + (k - 256)) * 128 + c];
            o = W7T; off = j;
        }
        o[off] = __float2half_rn(v);
    } else if (i < convTotal) {  // x conversion
        int j = i - 122880;
        int row = j >> 6, c = j & 63;
        __half h = __float2half_rn(x[j]);
        xh[j] = h;
        Vf[(size_t)row * 320 + 256 + c] = h;
    } else {  // degree count + within-node rank
        int j = i - convTotal;
        if (j < e) eoff[j] = atomicAdd(&cnt[dst[j]], 1);
    }
}

// ---------------- fused scan (13 blocks, sentinel lookback) ----------------
__global__ void scan_fused_kernel(const int* __restrict__ cnt, int n, int* __restrict__ bsum,
                                  int* __restrict__ rowptr, float* __restrict__ dis) {
    int tid = threadIdx.x;
    int lane = tid & 31, warp = tid >> 5;
    int base = (blockIdx.x * 256 + tid) * 16;
    int vals[16];
    int s = 0;
#pragma unroll
    for (int i = 0; i < 16; i++) {
        int idx = base + i;
        vals[i] = (idx < n) ? cnt[idx] : 0;
        s += vals[i];
    }
    int incl = s;
#pragma unroll
    for (int o = 1; o < 32; o <<= 1) {
        int t = __shfl_up_sync(0xffffffffu, incl, o);
        if (lane >= o) incl += t;
    }
    __shared__ int wsum[8];
    if (lane == 31) wsum[warp] = incl;
    __syncthreads();
    int woff = 0, total = 0;
#pragma unroll
    for (int w = 0; w < 8; w++) {
        if (w < warp) woff += wsum[w];
        total += wsum[w];
    }
    __shared__ int sPre;
    if (tid == 0) {
        atomicExch(&bsum[blockIdx.x], total + 1);
        int pre = 0;
        for (int w = 0; w < (int)blockIdx.x; w++) {
            int v;
            do { v = atomicAdd(&bsum[w], 0); } while (v == 0);
            pre += v - 1;
        }
        sPre = pre;
    }
    __syncthreads();
    int excl = sPre + woff + (incl - s);
#pragma unroll
    for (int i = 0; i < 16; i++) {
        int idx = base + i;
        if (idx < n) {
            rowptr[idx] = excl;
            dis[idx] = rsqrtf((float)(vals[i] + 1));
            excl += vals[i];
        }
    }
    if (blockIdx.x == gridDim.x - 1 && tid == 0) rowptr[n] = sPre + total;
}

// ---------------- CSR fill (atomic-free) ----------------
__global__ void fill_kernel(const int* __restrict__ src, const int* __restrict__ dst, int e,
                            const int* __restrict__ rowptr, const int* __restrict__ eoff,
                            int* __restrict__ csrsrc, float* __restrict__ csrnorm,
                            const float* __restrict__ dis) {
    int i = blockIdx.x * blockDim.x + threadIdx.x;
    if (i >= e) return;
    int d = dst[i], s = src[i];
    int p = rowptr[d] + eoff[i];
    csrsrc[p] = s;
    csrnorm[p] = dis[s] * dis[d];
}

// ---------------- HMMA mainloop (pure fp16, 128x128x32) ----------------
__device__ __forceinline__ void gemm_mainloop(
    const __half* __restrict__ A, int lda,
    const __half* __restrict__ B,
    int K, int n, int rowBase, int colBase,
    __half (*As)[128 * 40], __half (*Bs)[128 * 40],
    float acc[4][4][4]) {
    int tid = threadIdx.x;
    int lane = tid & 31, warp = tid >> 5;
    int warpM = warp & 1, warpN = warp >> 1;
    int total = K >> 5;

    auto loadChunk = [&](int kc, int buf) {
        int k0 = kc << 5;
        uint32_t aB = smem_u32(&As[buf][0]);
        uint32_t bB = smem_u32(&Bs[buf][0]);
#pragma unroll
        for (int i = 0; i < 2; i++) {
            int idx = tid + (i << 8);
            int row = idx >> 2, quad = idx & 3;
            cpasync16(aB + (row * 40 + quad * 8) * 2,
                      A + (size_t)(rowBase + row) * lda + k0 + quad * 8,
                      (rowBase + row) < n);
            cpasync16(bB + (row * 40 + quad * 8) * 2,
                      B + (size_t)(colBase + row) * K + k0 + quad * 8, true);
        }
        asm volatile("cp.async.commit_group;");
    };

    auto compute = [&](int buf) {
        uint32_t aB = smem_u32(&As[buf][0]);
        uint32_t bB = smem_u32(&Bs[buf][0]);
#pragma unroll
        for (int ks = 0; ks < 2; ks++) {
            uint32_t af[4][4], bf[4][2];
            int arow = warpM * 64 + (lane & 15);
            int acol = ks * 16 + (lane >> 4) * 8;
#pragma unroll
            for (int mi = 0; mi < 4; mi++)
                ldmx4(af[mi][0], af[mi][1], af[mi][2], af[mi][3],
                      aB + ((arow + mi * 16) * 40 + acol) * 2);
#pragma unroll
            for (int np = 0; np < 2; np++) {
                int brow = warpN * 32 + np * 16 + (lane & 7) + ((lane >> 4) << 3);
                int bcol = ks * 16 + (((lane >> 3) & 1) << 3);
                ldmx4(bf[np * 2][0], bf[np * 2][1], bf[np * 2 + 1][0], bf[np * 2 + 1][1],
                      bB + (brow * 40 + bcol) * 2);
            }
#pragma unroll
            for (int mi = 0; mi < 4; mi++)
#pragma unroll
                for (int ni = 0; ni < 4; ni++) mma16816(acc[mi][ni], af[mi], bf[ni]);
        }
    };

    loadChunk(0, 0);
    for (int tc = 0; tc < total; tc++) {
        int buf = tc & 1;
        if (tc + 1 < total) {
            loadChunk(tc + 1, buf ^ 1);
            asm volatile("cp.async.wait_group 1;");
        } else {
            asm volatile("cp.async.wait_group 0;");
        }
        __syncthreads();
        compute(buf);
        __syncthreads();
    }
}

// ---------------- epilogues ----------------
__device__ __forceinline__ void epi_colmax(float acc[4][4][4], int n, int rBase, int cBase,
                                           int lane, const float* __restrict__ addvec,
                                           int* __restrict__ mv) {
    float cm[8];
#pragma unroll
    for (int j = 0; j < 8; j++) cm[j] = -1e30f;
#pragma unroll
    for (int mi = 0; mi < 4; mi++) {
        int r0 = rBase + mi * 16 + (lane >> 2);
        int r1 = r0 + 8;
#pragma unroll
        for (int ni = 0; ni < 4; ni++) {
            int col = cBase + ni * 8 + (lane & 3) * 2;
            float v0 = (r0 < n) ? tanhf(acc[mi][ni][0] + addvec[col]) : -1e30f;
            float v1 = (r0 < n) ? tanhf(acc[mi][ni][1] + addvec[col + 1]) : -1e30f;
            float v2 = (r1 < n) ? tanhf(acc[mi][ni][2] + addvec[col]) : -1e30f;
            float v3 = (r1 < n) ? tanhf(acc[mi][ni][3] + addvec[col + 1]) : -1e30f;
            cm[ni * 2] = fmaxf(cm[ni * 2], fmaxf(v0, v2));
            cm[ni * 2 + 1] = fmaxf(cm[ni * 2 + 1], fmaxf(v1, v3));
        }
    }
#pragma unroll
    for (int off = 4; off < 32; off <<= 1)
#pragma unroll
        for (int j = 0; j < 8; j++)
            cm[j] = fmaxf(cm[j], __shfl_xor_sync(0xffffffffu, cm[j], off));
    if (lane < 4) {
#pragma unroll
        for (int ni = 0; ni < 4; ni++) {
            int col = cBase + ni * 8 + lane * 2;
            atomicMax(&mv[col], __float_as_int(cm[ni * 2] + 2.0f));
            atomicMax(&mv[col + 1], __float_as_int(cm[ni * 2 + 1] + 2.0f));
        }
    }
}

// MODE 0: tanh(acc+addvec) -> half | MODE 1: acc+addvec -> half
template <int MODE>
__device__ __forceinline__ void epi_store_h(float acc[4][4][4], int n, int rBase, int cBase,
                                            int lane, const float* __restrict__ addvec,
                                            __half* __restrict__ outH, int ldO) {
#pragma unroll
    for (int mi = 0; mi < 4; mi++) {
#pragma unroll
        for (int h = 0; h < 2; h++) {
            int r = rBase + mi * 16 + (lane >> 2) + h * 8;
            if (r >= n) continue;
#pragma unroll
            for (int ni = 0; ni < 4; ni++) {
                int col = cBase + ni * 8 + (lane & 3) * 2;
                float v0 = acc[mi][ni][h * 2] + addvec[col];
                float v1 = acc[mi][ni][h * 2 + 1] + addvec[col + 1];
                if (MODE == 0) { v0 = tanhf(v0); v1 = tanhf(v1); }
                *(__half2*)(outH + (size_t)r * ldO + col) =
                    __halves2half2(__float2half_rn(v0), __float2half_rn(v1));
            }
        }
    }
}

// ---------------- GEMM 1 ----------------
__global__ __launch_bounds__(256)
void hmma_gemm1(const __half* __restrict__ A, int lda, const __half* __restrict__ B,
                int K, int n, __half* __restrict__ outH, int ldO,
                const float* __restrict__ addvec) {
    __shared__ __align__(16) __half As[2][128 * 40];
    __shared__ __align__(16) __half Bs[2][128 * 40];
    float acc[4][4][4];
#pragma unroll
    for (int a = 0; a < 4; a++)
#pragma unroll
        for (int b = 0; b < 4; b++)
#pragma unroll
            for (int c = 0; c < 4; c++) acc[a][b][c] = 0.0f;
    int rowBase = blockIdx.x * 128, colBase = blockIdx.y * 128;
    gemm_mainloop(A, lda, B, K, n, rowBase, colBase, As, Bs, acc);
    int lane = threadIdx.x & 31, warp = threadIdx.x >> 5;
    int rBase = rowBase + (warp & 1) * 64, cBase = colBase + (warp >> 1) * 32;
    epi_store_h<0>(acc, n, rBase, cBase, lane, addvec, outH, ldO);
}

// ---------------- GEMM 7 (cvec in-kernel) ----------------
__global__ __launch_bounds__(256)
void hmma_gemm7(const __half* __restrict__ A, int lda, const __half* __restrict__ B,
                int K, int n, __half* __restrict__ outH, int ldO,
                const int* __restrict__ mv, const float* __restrict__ W7) {
    __shared__ __align__(16) __half As[2][128 * 40];
    __shared__ __align__(16) __half Bs[2][128 * 40];
    __shared__ float sAdd[128];
    int tid = threadIdx.x;
    if (tid < 128) {
        float s = 0.0f;
        for (int k = 0; k < 256; k++)
            s += (__int_as_float(mv[k]) - 2.0f) * W7[(size_t)k * 128 + tid];
        sAdd[tid] = s;
    }
    float acc[4][4][4];
#pragma unroll
    for (int a = 0; a < 4; a++)
#pragma unroll
        for (int b = 0; b < 4; b++)
#pragma unroll
            for (int c = 0; c < 4; c++) acc[a][b][c] = 0.0f;
    int rowBase = blockIdx.x * 128;
    gemm_mainloop(A, lda, B, K, n, rowBase, 0, As, Bs, acc);
    int lane = tid & 31, warp = tid >> 5;
    int rBase = rowBase + (warp & 1) * 64, cBase = (warp >> 1) * 32;
    epi_store_h<1>(acc, n, rBase, cBase, lane, sAdd, outH, ldO);
}

// ---------------- merged U/V GEMM (z=0: colmax; z=1: V -> half) ----------------
__global__ __launch_bounds__(256)
void hmma_gemm_uv(const __half* __restrict__ agg1,
                  const __half* __restrict__ W2T, const __half* __restrict__ W4T,
                  int n, const float* __restrict__ b2, const float* __restrict__ b4,
                  __half* __restrict__ Vf, int* __restrict__ mv) {
    __shared__ __align__(16) __half As[2][128 * 40];
    __shared__ __align__(16) __half Bs[2][128 * 40];
    float acc[4][4][4];
#pragma unroll
    for (int a = 0; a < 4; a++)
#pragma unroll
        for (int b = 0; b < 4; b++)
#pragma unroll
            for (int c = 0; c < 4; c++) acc[a][b][c] = 0.0f;
    int z = blockIdx.z;
    const __half* A = agg1 + (z ? 128 : 0);
    const __half* B = z ? W4T : W2T;
    int rowBase = blockIdx.x * 128, colBase = blockIdx.y * 128;
    gemm_mainloop(A, 256, B, 128, n, rowBase, colBase, As, Bs, acc);
    int lane = threadIdx.x & 31, warp = threadIdx.x >> 5;
    int rBase = rowBase + (warp & 1) * 64, cBase = colBase + (warp >> 1) * 32;
    if (z == 0) {
        epi_colmax(acc, n, rBase, cBase, lane, b2, mv);
    } else {
        epi_store_h<0>(acc, n, rBase, cBase, lane, b4, Vf, 320);
    }
}

// ---------------- agg F=64 (edge-unrolled x4) ----------------
__global__ void agg64_kernel(const __half* __restrict__ h, const int* __restrict__ rowptr,
                             const int* __restrict__ csrsrc, const float* __restrict__ csrnorm,
                             const float* __restrict__ dis, __half* __restrict__ out, int n) {
    int warp = (blockIdx.x * blockDim.x + threadIdx.x) >> 5;
    int lane = threadIdx.x & 31;
    if (warp >= n) return;
    float2 acc = make_float2(0.f, 0.f);
    int s0 = rowptr[warp], s1 = rowptr[warp + 1];
    int j = s0;
    for (; j + 3 < s1; j += 4) {
        int sa = csrsrc[j], sb = csrsrc[j + 1], sc = csrsrc[j + 2], sd = csrsrc[j + 3];
        float wa = csrnorm[j], wb = csrnorm[j + 1], wc = csrnorm[j + 2], wd = csrnorm[j + 3];
        float2 va = __half22float2(*(const __half2*)(h + (size_t)sa * 64 + lane * 2));
        float2 vb = __half22float2(*(const __half2*)(h + (size_t)sb * 64 + lane * 2));
        float2 vc = __half22float2(*(const __half2*)(h + (size_t)sc * 64 + lane * 2));
        float2 vd = __half22float2(*(const __half2*)(h + (size_t)sd * 64 + lane * 2));
        acc.x += va.x * wa + vb.x * wb + vc.x * wc + vd.x * wd;
        acc.y += va.y * wa + vb.y * wb + vc.y * wc + vd.y * wd;
    }
    for (; j < s1; j++) {
        int s = csrsrc[j];
        float w = csrnorm[j];
        float2 va = __half22float2(*(const __half2*)(h + (size_t)s * 64 + lane * 2));
        acc.x += va.x * w;
        acc.y += va.y * w;
    }
    float ds = dis[warp];
    float w2 = ds * ds;
    float2 v = __half22float2(*(const __half2*)(h + (size_t)warp * 64 + lane * 2));
    acc.x += v.x * w2;
    acc.y += v.y * w2;
    *(__half2*)(out + (size_t)warp * 64 + lane * 2) =
        __halves2half2(__float2half_rn(acc.x), __float2half_rn(acc.y));
}

// ---------------- agg F=256 (edge-unrolled x4) ----------------
__global__ void agg256_kernel(const __half* __restrict__ h, const int* __restrict__ rowptr,
                              const int* __restrict__ csrsrc, const float* __restrict__ csrnorm,
                              const float* __restrict__ dis, __half* __restrict__ out, int n) {
    int warp = (blockIdx.x * blockDim.x + threadIdx.x) >> 5;
    int lane = threadIdx.x & 31;
    if (warp >= n) return;
    float acc[8] = {0.f, 0.f, 0.f, 0.f, 0.f, 0.f, 0.f, 0.f};
    int s0 = rowptr[warp], s1 = rowptr[warp + 1];
    int i0 = lane * 8;
    int j = s0;
    for (; j + 3 < s1; j += 4) {
        int sa = csrsrc[j], sb = csrsrc[j + 1], sc = csrsrc[j + 2], sd = csrsrc[j + 3];
        float wa = csrnorm[j], wb = csrnorm[j + 1], wc = csrnorm[j + 2], wd = csrnorm[j + 3];
        uint4 ra = *(const uint4*)(h + (size_t)sa * 256 + i0);
        uint4 rb = *(const uint4*)(h + (size_t)sb * 256 + i0);
        uint4 rc = *(const uint4*)(h + (size_t)sc * 256 + i0);
        uint4 rd = *(const uint4*)(h + (size_t)sd * 256 + i0);
        const __half2 *ha = (const __half2*)&ra, *hb = (const __half2*)&rb;
        const __half2 *hc = (const __half2*)&rc, *hd = (const __half2*)&rd;
#pragma unroll
        for (int q = 0; q < 4; q++) {
            float2 fa = __half22float2(ha[q]);
            float2 fb = __half22float2(hb[q]);
            float2 fc = __half22float2(hc[q]);
            float2 fd = __half22float2(hd[q]);
            acc[q * 2] += fa.x * wa + fb.x * wb + fc.x * wc + fd.x * wd;
            acc[q * 2 + 1] += fa.y * wa + fb.y * wb + fc.y * wc + fd.y * wd;
        }
    }
    for (; j < s1; j++) {
        int s = csrsrc[j];
        float w = csrnorm[j];
        uint4 raw = *(const uint4*)(h + (size_t)s * 256 + i0);
        const __half2* hp = (const __half2*)&raw;
#pragma unroll
        for (int q = 0; q < 4; q++) {
            float2 f = __half22float2(hp[q]);
            acc[q * 2] += f.x * w;
            acc[q * 2 + 1] += f.y * w;
        }
    }
    float ds = dis[warp];
    float w2 = ds * ds;
    uint4 raw = *(const uint4*)(h + (size_t)warp * 256 + i0);
    const __half2* hp = (const __half2*)&raw;
#pragma unroll
    for (int q = 0; q < 4; q++) {
        float2 f = __half22float2(hp[q]);
        acc[q * 2] += f.x * w2;
        acc[q * 2 + 1] += f.y * w2;
    }
    uint4 o;
    __half2* op = (__half2*)&o;
#pragma unroll
    for (int q = 0; q < 4; q++)
        op[q] = __halves2half2(__float2half_rn(acc[q * 2]), __float2half_rn(acc[q * 2 + 1]));
    *(uint4*)(out + (size_t)warp * 256 + i0) = o;
}

// ---------------- agg F=128 + bias + tanh (edge-unrolled x4, fp32 out) ----------------
__global__ void agg128t_kernel(const __half* __restrict__ h, const int* __restrict__ rowptr,
                               const int* __restrict__ csrsrc, const float* __restrict__ csrnorm,
                               const float* __restrict__ dis, const float* __restrict__ bias,
                               float* __restrict__ out, int n) {
    int warp = (blockIdx.x * blockDim.x + threadIdx.x) >> 5;
    int lane = threadIdx.x & 31;
    if (warp >= n) return;
    float4 acc = make_float4(0.f, 0.f, 0.f, 0.f);
    int s0 = rowptr[warp], s1 = rowptr[warp + 1];
    int idx = lane << 2;
    int j = s0;
    for (; j + 3 < s1; j += 4) {
        int sa = csrsrc[j], sb = csrsrc[j + 1], sc = csrsrc[j + 2], sd = csrsrc[j + 3];
        float wa = csrnorm[j], wb = csrnorm[j + 1], wc = csrnorm[j + 2], wd = csrnorm[j + 3];
        uint2 ra = *(const uint2*)(h + (size_t)sa * 128 + idx);
        uint2 rb = *(const uint2*)(h + (size_t)sb * 128 + idx);
        uint2 rc = *(const uint2*)(h + (size_t)sc * 128 + idx);
        uint2 rd = *(const uint2*)(h + (size_t)sd * 128 + idx);
        float2 a0 = __half22float2(*(const __half2*)&ra.x);
        float2 a1 = __half22float2(*(const __half2*)&ra.y);
        float2 b0 = __half22float2(*(const __half2*)&rb.x);
        float2 b1 = __half22float2(*(const __half2*)&rb.y);
        float2 c0 = __half22float2(*(const __half2*)&rc.x);
        float2 c1 = __half22float2(*(const __half2*)&rc.y);
        float2 d0 = __half22float2(*(const __half2*)&rd.x);
        float2 d1 = __half22float2(*(const __half2*)&rd.y);
        acc.x += a0.x * wa + b0.x * wb + c0.x * wc + d0.x * wd;
        acc.y += a0.y * wa + b0.y * wb + c0.y * wc + d0.y * wd;
        acc.z += a1.x * wa + b1.x * wb + c1.x * wc + d1.x * wd;
        acc.w += a1.y * wa + b1.y * wb + c1.y * wc + d1.y * wd;
    }
    for (; j < s1; j++) {
        int s = csrsrc[j];
        float w = csrnorm[j];
        uint2 ra = *(const uint2*)(h + (size_t)s * 128 + idx);
        float2 a0 = __half22float2(*(const __half2*)&ra.x);
        float2 a1 = __half22float2(*(const __half2*)&ra.y);
        acc.x += a0.x * w; acc.y += a0.y * w; acc.z += a1.x * w; acc.w += a1.y * w;
    }
    float ds = dis[warp];
    float w2 = ds * ds;
    uint2 rv = *(const uint2*)(h + (size_t)warp * 128 + idx);
    float2 v0 = __half22float2(*(const __half2*)&rv.x);
    float2 v1 = __half22float2(*(const __half2*)&rv.y);
    float4 bb = *(const float4*)(bias + idx);
    float4 r;
    r.x = tanhf(acc.x + v0.x * w2 + bb.x);
    r.y = tanhf(acc.y + v0.y * w2 + bb.y);
    r.z = tanhf(acc.z + v1.x * w2 + bb.z);
    r.w = tanhf(acc.w + v1.y * w2 + bb.w);
    *(float4*)(out + (size_t)warp * 128 + idx) = r;
}

extern "C" void kernel_launch(void* const* d_in, const int* in_sizes, int n_in,
                              void* d_out, int out_size) {
    const float* x = (const float*)d_in[0];
    const int* ei = (const int*)d_in[1];
    const float* W1 = (const float*)d_in[3];
    const float* b1 = (const float*)d_in[4];
    const float* W2 = (const float*)d_in[5];
    const float* b2 = (const float*)d_in[6];
    const float* W3 = (const float*)d_in[7];
    const float* b3 = (const float*)d_in[8];
    const float* W4 = (const float*)d_in[9];
    const float* b4 = (const float*)d_in[10];
    const float* W7 = (const float*)d_in[11];
    const float* b7 = (const float*)d_in[12];

    int n = in_sizes[0] / 64;
    int e = in_sizes[1] / 2;
    const int* src = ei;
    const int* dst = ei + e;
    float* out = (float*)d_out;

    __half *xh, *agg0, *T1, *agg1, *Vf, *H, *WcT, *W2T, *W4T, *W7T;
    float *dis, *csrnorm, *bc;
    int *cnt, *rowptr, *csrsrc, *eoff, *mv, *bsum;
    cudaGetSymbolAddress((void**)&xh, g_xh);
    cudaGetSymbolAddress((void**)&agg0, g_agg0);
    cudaGetSymbolAddress((void**)&T1, g_T1);
    cudaGetSymbolAddress((void**)&agg1, g_agg1);
    cudaGetSymbolAddress((void**)&Vf, g_Vf);
    cudaGetSymbolAddress((void**)&H, g_H);
    cudaGetSymbolAddress((void**)&dis, g_dis);
    cudaGetSymbolAddress((void**)&cnt, g_cnt);
    cudaGetSymbolAddress((void**)&rowptr, g_rowptr);
    cudaGetSymbolAddress((void**)&csrsrc, g_csrsrc);
    cudaGetSymbolAddress((void**)&eoff, g_eoff);
    cudaGetSymbolAddress((void**)&csrnorm, g_csrnorm);
    cudaGetSymbolAddress((void**)&bsum, g_bsum);
    cudaGetSymbolAddress((void**)&mv, g_mv);
    cudaGetSymbolAddress((void**)&WcT, g_WcT);
    cudaGetSymbolAddress((void**)&W2T, g_W2T);
    cudaGetSymbolAddress((void**)&W4T, g_W4T);
    cudaGetSymbolAddress((void**)&W7T, g_W7T);
    cudaGetSymbolAddress((void**)&bc, g_bc);

    int eb = (e + 255) / 256;
    int aggBlocks = (n + 7) / 8;
    int gm = (n + 127) / 128;
    int nb = (n + 4095) / 4096;
    int mergedTotal = 122880 + n * 64 + e;
    dim3 g2(gm, 2), guv(gm, 2, 2);

    // init (cnt only) + merged conv/count (+ bsum/mv zeroing) + scan + fill
    cudaMemsetAsync(cnt, 0, (size_t)n * sizeof(int));
    conv_count_kernel<<<(mergedTotal + 255) / 256, 256>>>(
        W1, W3, W2, W4, W7, b1, b3, x, WcT, W2T, W4T, W7T, bc, xh, Vf, n * 64,
        dst, e, cnt, eoff, bsum, mv);
    scan_fused_kernel<<<nb, 256>>>(cnt, n, bsum, rowptr, dis);
    fill_kernel<<<eb, 256>>>(src, dst, e, rowptr, eoff, csrsrc, csrnorm, dis);

    // agg0 = P x
    agg64_kernel<<<aggBlocks, 256>>>(xh, rowptr, csrsrc, csrnorm, dis, agg0, n);
    // T1 = tanh(agg0 @ [W1|W3] + [b1|b3])
    hmma_gemm1<<<g2, 256>>>(agg0, 64, WcT, 64, n, T1, 256, bc);
    // agg1 = P T1
    agg256_kernel<<<aggBlocks, 256>>>(T1, rowptr, csrsrc, csrnorm, dis, agg1, n);
    // merged: z=0 colmax -> mv; z=1 V -> Vf
    hmma_gemm_uv<<<guv, 256>>>(agg1, W2T, W4T, n, b2, b4, Vf, mv);
    // H = [V|xh] @ W7T + cvec
    hmma_gemm7<<<gm, 256>>>(Vf, 320, W7T, 320, n, H, 128, mv, W7);
    // out = tanh(P H + b7)
    agg128t_kernel<<<aggBlocks, 256>>>(H, rowptr, csrsrc, csrnorm, dis, b7, out, n);
}